// round 16
// baseline (speedup 1.0000x reference)
#include <cuda_runtime.h>
#include <cuda_bf16.h>
#include <cstdint>
#include <math.h>

// Problem constants
#define BB 8
#define NN 16384
#define SSZ 2048
#define C1V 128
#define C2V 256
#define CF 384
#define MM (BB*NN)      /* 131072 rows */
#define OO 256          /* output channels per layer */
#define P2R (BB*SSZ)    /* 16384 points2 rows */

// -------- scratch (static device globals; ~308MB, below proven-safe 331MB) --------
// pool (134MB): phase1: p1h = [0, MM*128), p1l = [MM*128, 2*MM*128)
//               phase2: Bh  = [0, MM*256), Bl  = [MM*256, 2*MM*256)
__device__ __align__(16) __nv_bfloat16 g_ab[(size_t)2 * MM * OO];
__device__ __align__(16) float         g_h[(size_t)MM * OO];       // 134MB pre-BN h
__device__ __align__(16) float         g_p2proj[(size_t)P2R * OO]; // 16.8MB
__device__ __align__(16) __nv_bfloat16 g_p2h[(size_t)P2R * C2V];   // 8.4MB
__device__ __align__(16) __nv_bfloat16 g_p2l[(size_t)P2R * C2V];   // 8.4MB
__device__ __align__(16) float         g_knn[(size_t)MM * 8];      // 4MB idx+w
__device__ __align__(16) __nv_bfloat16 g_w1ah[OO * C1V], g_w1al[OO * C1V];
__device__ __align__(16) __nv_bfloat16 g_w1bh[OO * C2V], g_w1bl[OO * C2V];
__device__ __align__(16) __nv_bfloat16 g_w2h[OO * OO],  g_w2l[OO * OO];
__device__ __align__(16) float g_part[1024 * 512];                 // 2MB
__device__ __align__(16) float g_s1[OO], g_t1[OO], g_s2[OO], g_t2[OO];

// ======================================================================
// helpers (NO 'a'-suffix features)
// ======================================================================
__device__ __forceinline__ uint32_t smem_u32(const void* p) {
    uint32_t a;
    asm("{ .reg .u64 t; cvta.to.shared.u64 t, %1; cvt.u32.u64 %0, t; }" : "=r"(a) : "l"(p));
    return a;
}
__device__ __forceinline__ void cp_async16(uint32_t dst, const void* src) {
    asm volatile("cp.async.cg.shared.global [%0], [%1], 16;" :: "r"(dst), "l"(src));
}
#define CP_COMMIT() asm volatile("cp.async.commit_group;" ::: "memory")
#define CP_WAIT1()  asm volatile("cp.async.wait_group 1;" ::: "memory")
#define CP_WAIT0()  asm volatile("cp.async.wait_group 0;" ::: "memory")

#define LDSM4(r0, r1, r2, r3, addr) \
    asm volatile("ldmatrix.sync.aligned.m8n8.x4.shared.b16 {%0,%1,%2,%3}, [%4];" \
                 : "=r"(r0), "=r"(r1), "=r"(r2), "=r"(r3) : "r"(addr))

__device__ __forceinline__ void mma_bf16(float* c, const uint32_t* a, const uint32_t* b) {
    asm volatile("mma.sync.aligned.m16n8k16.row.col.f32.bf16.bf16.f32 "
                 "{%0,%1,%2,%3}, {%4,%5,%6,%7}, {%8,%9}, {%0,%1,%2,%3};"
                 : "+f"(c[0]), "+f"(c[1]), "+f"(c[2]), "+f"(c[3])
                 : "r"(a[0]), "r"(a[1]), "r"(a[2]), "r"(a[3]), "r"(b[0]), "r"(b[1]));
}

// bf16 hi/lo split (proven: rel_err 9.6e-6 end to end with 3-term products)
__device__ __forceinline__ void split_bf(float v, __nv_bfloat16& h, __nv_bfloat16& l) {
    h = __float2bfloat16_rn(v);
    l = __float2bfloat16_rn(v - __bfloat162float(h));
}

// ======================================================================
// Kernel 1: 3-NN (EXACT-DIFFERENCE distance — proven selection) + p1 split.
// 2 queries per thread for ILP; candidate LDS amortized over both.
// Expanded |q|^2-2p.q form flips neighbor ordering (1.4e-3). Never use it.
// ======================================================================
__global__ void knn_kernel(const float* __restrict__ xyz1,
                           const float* __restrict__ xyz2,
                           const float* __restrict__ points1) {
    __shared__ float4 s4[SSZ];

    const int tid = threadIdx.x;
    const int b   = blockIdx.y;
    const int n0  = blockIdx.x * 512;

    const float* x2 = xyz2 + (size_t)b * SSZ * 3;
    for (int s = tid; s < SSZ; s += 256) {
        s4[s] = make_float4(x2[3*s], x2[3*s+1], x2[3*s+2], 0.f);
    }
    __syncthreads();

    const int nA = n0 + tid;
    const int nB = nA + 256;
    const float* pA = xyz1 + ((size_t)b * NN + nA) * 3;
    const float* pB = xyz1 + ((size_t)b * NN + nB) * 3;
    const float ax = pA[0], ay = pA[1], az = pA[2];
    const float bx = pB[0], by = pB[1], bz = pB[2];
    float a0 = 3.4e38f, a1 = 3.4e38f, a2 = 3.4e38f;
    float c0 = 3.4e38f, c1 = 3.4e38f, c2 = 3.4e38f;
    int   ja0 = 0, ja1 = 0, ja2 = 0, jb0 = 0, jb1 = 0, jb2 = 0;
    #pragma unroll 4
    for (int s = 0; s < SSZ; ++s) {
        float4 q = s4[s];
        float dxA = ax - q.x, dyA = ay - q.y, dzA = az - q.z;
        float dxB = bx - q.x, dyB = by - q.y, dzB = bz - q.z;
        float dA = dxA*dxA + dyA*dyA + dzA*dzA;
        float dB = dxB*dxB + dyB*dyB + dzB*dzB;
        if (dA < a2) {
            if (dA < a1) {
                a2 = a1; ja2 = ja1;
                if (dA < a0) { a1 = a0; ja1 = ja0; a0 = dA; ja0 = s; }
                else         { a1 = dA; ja1 = s; }
            } else { a2 = dA; ja2 = s; }
        }
        if (dB < c2) {
            if (dB < c1) {
                c2 = c1; jb2 = jb1;
                if (dB < c0) { c1 = c0; jb1 = jb0; c0 = dB; jb0 = s; }
                else         { c1 = dB; jb1 = s; }
            } else { c2 = dB; jb2 = s; }
        }
    }

    auto emit = [&](int n, float d0, float d1, float d2, int j0, int j1, int j2) {
        float r0 = 1.f / (sqrtf(d0) + 1e-8f);
        float r1 = 1.f / (sqrtf(d1) + 1e-8f);
        float r2 = 1.f / (sqrtf(d2) + 1e-8f);
        float rs = 1.f / (r0 + r1 + r2);
        const size_t row = (size_t)b * NN + n;
        float4 ia, wa;
        ia.x = __int_as_float(b * SSZ + j0);
        ia.y = __int_as_float(b * SSZ + j1);
        ia.z = __int_as_float(b * SSZ + j2);
        ia.w = 0.f;
        wa.x = r0 * rs; wa.y = r1 * rs; wa.z = r2 * rs; wa.w = 0.f;
        ((float4*)g_knn)[row * 2]     = ia;
        ((float4*)g_knn)[row * 2 + 1] = wa;
    };
    emit(nA, a0, a1, a2, ja0, ja1, ja2);
    emit(nB, c0, c1, c2, jb0, jb1, jb2);

    // points1 -> bf16 split into pool (512 rows per block)
    __nv_bfloat16* p1h = g_ab;
    __nv_bfloat16* p1l = g_ab + (size_t)MM * C1V;
    const float4* p1 = (const float4*)(points1 + ((size_t)b * NN + n0) * C1V);
    for (int i = tid; i < 512 * 32; i += 256) {
        float4 v = p1[i];
        union { __nv_bfloat16 bv[4]; uint2 u; } H, L;
        split_bf(v.x, H.bv[0], L.bv[0]);
        split_bf(v.y, H.bv[1], L.bv[1]);
        split_bf(v.z, H.bv[2], L.bv[2]);
        split_bf(v.w, H.bv[3], L.bv[3]);
        const size_t off4 = ((size_t)b * NN + n0) * 32 + i;
        ((uint2*)p1h)[off4] = H.u;
        ((uint2*)p1l)[off4] = L.u;
    }
}

// ======================================================================
// converts
// ======================================================================
__global__ void wconvert_kernel(const float* __restrict__ W1,
                                const float* __restrict__ W2) {
    int i = blockIdx.x * 256 + threadIdx.x;
    if (i < OO * CF) {
        int o = i / CF, c = i - o * CF;
        __nv_bfloat16 h, l; split_bf(W1[i], h, l);
        if (c < C1V) { g_w1ah[o * C1V + c] = h; g_w1al[o * C1V + c] = l; }
        else         { g_w1bh[o * C2V + c - C1V] = h; g_w1bl[o * C2V + c - C1V] = l; }
    }
    if (i < OO * OO) { __nv_bfloat16 h, l; split_bf(W2[i], h, l); g_w2h[i] = h; g_w2l[i] = l; }
}

__global__ void p2convert_kernel(const float* __restrict__ points2) {
    const size_t i = (size_t)blockIdx.x * 256 + threadIdx.x;
    float4 v = ((const float4*)points2)[i];
    union { __nv_bfloat16 bv[4]; uint2 u; } H, L;
    split_bf(v.x, H.bv[0], L.bv[0]);
    split_bf(v.y, H.bv[1], L.bv[1]);
    split_bf(v.z, H.bv[2], L.bv[2]);
    split_bf(v.w, H.bv[3], L.bv[3]);
    ((uint2*)g_p2h)[i] = H.u;
    ((uint2*)g_p2l)[i] = L.u;
}

// ======================================================================
// GEMM core (round-9/15, best measured): CTA 128x128, 512 threads / 16 warps
// (4m x 4n), warp 32x32, bf16 3-term, presplit cp.async, 3-stage.
// GRID ORDER: x = N-block (2), y = m-tile — adjacent blocks share the A tile
// so the second N-half's A-read hits L2 instead of DRAM.
// ======================================================================
#define ROWP 80
#define TILE_B (128 * ROWP)
#define STAGE_B (4 * TILE_B)
#define GSMEM   (3 * STAGE_B)      /* 122880 */
#define NTHR 512

struct FragIdx { uint32_t a_off, b_off; };
__device__ __forceinline__ FragIdx frag_idx(int lane) {
    const int g = lane >> 3, l7 = lane & 7;
    FragIdx f;
    f.a_off = (uint32_t)((l7 + (g & 1) * 8) * ROWP + (g >> 1) * 16);
    f.b_off = (uint32_t)(((g >> 1) * 8 + l7) * ROWP + (g & 1) * 16);
    return f;
}

__device__ __forceinline__ void compute_stage(uint32_t base, int warp_m, int warp_n,
                                              const FragIdx& f, float acc[2][4][4]) {
    #pragma unroll
    for (int ks = 0; ks < 2; ks++) {
        uint32_t ah[2][4], al[2][4], w[4][2];
        #pragma unroll
        for (int tm = 0; tm < 2; tm++) {
            const uint32_t ad = base + f.a_off + (uint32_t)((warp_m + tm * 16) * ROWP + ks * 32);
            LDSM4(ah[tm][0], ah[tm][1], ah[tm][2], ah[tm][3], ad);
            LDSM4(al[tm][0], al[tm][1], al[tm][2], al[tm][3], ad + TILE_B);
        }
        #pragma unroll
        for (int tp = 0; tp < 2; tp++) {
            const uint32_t bd = base + 2 * TILE_B + f.b_off
                              + (uint32_t)((warp_n + tp * 16) * ROWP + ks * 32);
            LDSM4(w[2*tp][0], w[2*tp][1], w[2*tp+1][0], w[2*tp+1][1], bd);
        }
        #pragma unroll
        for (int tm = 0; tm < 2; tm++)
            #pragma unroll
            for (int tn = 0; tn < 4; tn++) mma_bf16(acc[tm][tn], ah[tm], w[tn]);
        #pragma unroll
        for (int tm = 0; tm < 2; tm++)
            #pragma unroll
            for (int tn = 0; tn < 4; tn++) mma_bf16(acc[tm][tn], al[tm], w[tn]);
        #pragma unroll
        for (int tp = 0; tp < 2; tp++) {
            const uint32_t bd = base + 3 * TILE_B + f.b_off
                              + (uint32_t)((warp_n + tp * 16) * ROWP + ks * 32);
            LDSM4(w[2*tp][0], w[2*tp][1], w[2*tp+1][0], w[2*tp+1][1], bd);
        }
        #pragma unroll
        for (int tm = 0; tm < 2; tm++)
            #pragma unroll
            for (int tn = 0; tn < 4; tn++) mma_bf16(acc[tm][tn], ah[tm], w[tn]);
    }
}

template<bool BIAS, bool GATHER, bool PART>
__device__ __forceinline__ void gemm_epilogue(float acc[2][4][4], char* smem,
                                              int tid, int wid, int lane,
                                              int m0, int n0, int warp_m, int warp_n,
                                              const float* bias, float* C) {
    if (BIAS) {
        #pragma unroll
        for (int tn = 0; tn < 4; tn++) {
            float2 bv = *(const float2*)(bias + n0 + warp_n + tn * 8 + (lane & 3) * 2);
            #pragma unroll
            for (int tm = 0; tm < 2; tm++) {
                acc[tm][tn][0] += bv.x; acc[tm][tn][1] += bv.y;
                acc[tm][tn][2] += bv.x; acc[tm][tn][3] += bv.y;
            }
        }
    }
    if (GATHER) {
        #pragma unroll
        for (int tm = 0; tm < 2; tm++) {
            const int r_lo = m0 + warp_m + tm * 16 + (lane >> 2);
            const int r_hi = r_lo + 8;
            float4 ia = ((const float4*)g_knn)[(size_t)r_lo * 2];
            float4 wa = ((const float4*)g_knn)[(size_t)r_lo * 2 + 1];
            float4 ib = ((const float4*)g_knn)[(size_t)r_hi * 2];
            float4 wb = ((const float4*)g_knn)[(size_t)r_hi * 2 + 1];
            const int   gl[3] = { __float_as_int(ia.x), __float_as_int(ia.y), __float_as_int(ia.z) };
            const float wl[3] = { wa.x, wa.y, wa.z };
            const int   gh[3] = { __float_as_int(ib.x), __float_as_int(ib.y), __float_as_int(ib.z) };
            const float wh[3] = { wb.x, wb.y, wb.z };
            #pragma unroll
            for (int k = 0; k < 3; k++) {
                const float* pl = g_p2proj + (size_t)gl[k] * OO + n0;
                const float* ph = g_p2proj + (size_t)gh[k] * OO + n0;
                #pragma unroll
                for (int tn = 0; tn < 4; tn++) {
                    const int col = warp_n + tn * 8 + (lane & 3) * 2;
                    float2 vl = *(const float2*)(pl + col);
                    float2 vh = *(const float2*)(ph + col);
                    acc[tm][tn][0] += wl[k] * vl.x; acc[tm][tn][1] += wl[k] * vl.y;
                    acc[tm][tn][2] += wh[k] * vh.x; acc[tm][tn][3] += wh[k] * vh.y;
                }
            }
        }
    }
    if (PART) {
        __syncthreads();
        float* sP  = (float*)smem;        // [4][128]
        float* ssP = sP + 512;            // [4][128]
        const int mg = wid & 3;
        #pragma unroll
        for (int tn = 0; tn < 4; tn++) {
            #pragma unroll
            for (int p = 0; p < 2; p++) {
                float s = 0.f, ss = 0.f;
                #pragma unroll
                for (int tm = 0; tm < 2; tm++) {
                    float a = acc[tm][tn][p], b = acc[tm][tn][2 + p];
                    s += a + b; ss += a * a + b * b;
                }
                #pragma unroll
                for (int o = 4; o <= 16; o <<= 1) {
                    s  += __shfl_xor_sync(0xFFFFFFFFu, s, o);
                    ss += __shfl_xor_sync(0xFFFFFFFFu, ss, o);
                }
                if (lane < 4) {
                    const int cl = warp_n + tn * 8 + (lane & 3) * 2 + p;
                    sP [mg * 128 + cl] = s;
                    ssP[mg * 128 + cl] = ss;
                }
            }
        }
        __syncthreads();
        if (tid < 128) {
            const float s  = sP[tid]  + sP[128 + tid]  + sP[256 + tid]  + sP[384 + tid];
            const float ss = ssP[tid] + ssP[128 + tid] + ssP[256 + tid] + ssP[384 + tid];
            // m-tile = blockIdx.y under the swapped grid
            g_part[(size_t)blockIdx.y * 512 + n0 + tid]       = s;
            g_part[(size_t)blockIdx.y * 512 + 256 + n0 + tid] = ss;
        }
    }
    #pragma unroll
    for (int tm = 0; tm < 2; tm++) {
        const int r0 = m0 + warp_m + tm * 16 + (lane >> 2);
        float* c0 = C + (size_t)r0 * OO + n0;
        #pragma unroll
        for (int tn = 0; tn < 4; tn++) {
            const int col = warp_n + tn * 8 + (lane & 3) * 2;
            *(float2*)(c0 + col)          = make_float2(acc[tm][tn][0], acc[tm][tn][1]);
            *(float2*)(c0 + 8 * OO + col) = make_float2(acc[tm][tn][2], acc[tm][tn][3]);
        }
    }
}

// ----- presplit GEMM body (cp.async Ah/Al/Wh/Wl), 3-stage -----
// grid: x = N-block, y = m-tile (L2 reuse of A between the two N-halves)
template<int K, bool BIAS, bool GATHER, bool PART>
__device__ __forceinline__ void gemm_body(const __nv_bfloat16* __restrict__ Ah,
                                          const __nv_bfloat16* __restrict__ Al,
                                          const __nv_bfloat16* __restrict__ Wh,
                                          const __nv_bfloat16* __restrict__ Wl,
                                          const float* __restrict__ bias,
                                          float* __restrict__ C) {
    extern __shared__ char smem[];
    constexpr int NC = K / 32;
    const uint32_t sb = smem_u32(smem);
    const int tid  = threadIdx.x;
    const int wid  = tid >> 5, lane = tid & 31;
    const int m0   = blockIdx.y << 7;
    const int n0   = blockIdx.x << 7;
    const int warp_m = (wid & 3) * 32;
    const int warp_n = (wid >> 2) * 32;

    const int lr = tid >> 2, lkg = tid & 3;
    const uint32_t l_dst = (uint32_t)(lr * ROWP + lkg * 16);
    const size_t   a_src0 = (size_t)(m0 + lr) * K + lkg * 8;
    const size_t   w_src0 = (size_t)(n0 + lr) * K + lkg * 8;
    const FragIdx f = frag_idx(lane);

    float acc[2][4][4];
    #pragma unroll
    for (int tm = 0; tm < 2; tm++)
        #pragma unroll
        for (int tn = 0; tn < 4; tn++)
            #pragma unroll
            for (int q = 0; q < 4; q++) acc[tm][tn][q] = 0.f;

    auto load_stage = [&](int s, int kc) {
        const uint32_t base = sb + s * STAGE_B;
        cp_async16(base + l_dst,              Ah + a_src0 + kc);
        cp_async16(base + l_dst + TILE_B,     Al + a_src0 + kc);
        cp_async16(base + l_dst + 2 * TILE_B, Wh + w_src0 + kc);
        cp_async16(base + l_dst + 3 * TILE_B, Wl + w_src0 + kc);
    };

    load_stage(0, 0);  CP_COMMIT();
    load_stage(1, 32); CP_COMMIT();

    for (int i = 0; i < NC; i++) {
        if (i + 1 < NC) { CP_WAIT1(); } else { CP_WAIT0(); }
        __syncthreads();
        if (i + 2 < NC) { load_stage((i + 2) % 3, (i + 2) * 32); CP_COMMIT(); }
        compute_stage(sb + (i % 3) * STAGE_B, warp_m, warp_n, f, acc);
    }
    gemm_epilogue<BIAS, GATHER, PART>(acc, smem, tid, wid, lane, m0, n0, warp_m, warp_n, bias, C);
}

__global__ void __launch_bounds__(NTHR, 1)
p2proj_kernel() {
    gemm_body<C2V, false, false, false>(g_p2h, g_p2l, g_w1bh, g_w1bl, nullptr, g_p2proj);
}
__global__ void __launch_bounds__(NTHR, 1)
gemm1_kernel(const float* __restrict__ bias) {
    gemm_body<C1V, true, true, true>(g_ab, g_ab + (size_t)MM * C1V, g_w1ah, g_w1al, bias, g_h);
}
__global__ void __launch_bounds__(NTHR, 1)
gemm2_kernel(const float* __restrict__ bias, float* __restrict__ C) {
    gemm_body<OO, true, false, true>(g_ab, g_ab + (size_t)MM * OO, g_w2h, g_w2l, bias, C);
}

// ======================================================================
// BN finalize over 1024 m-block partials; 32 blocks x 8 warps
// ======================================================================
__global__ void bn_finalize_kernel(const float* __restrict__ g,
                                   const float* __restrict__ be, int which) {
    const int w = threadIdx.x >> 5, l = threadIdx.x & 31;
    const int c = blockIdx.x * 8 + w;
    float s = 0.f, ss = 0.f;
    for (int b = l; b < 1024; b += 32) {
        s  += g_part[(size_t)b * 512 + c];
        ss += g_part[(size_t)b * 512 + 256 + c];
    }
    #pragma unroll
    for (int o = 16; o; o >>= 1) {
        s  += __shfl_xor_sync(0xFFFFFFFFu, s, o);
        ss += __shfl_xor_sync(0xFFFFFFFFu, ss, o);
    }
    if (l == 0) {
        const float mu  = s * (1.0f / (float)MM);
        const float var = ss * (1.0f / (float)MM) - mu * mu;
        const float inv = rsqrtf(var + 1e-5f);
        const float sc  = g[c] * inv;
        const float sh  = be[c] - mu * sc;
        if (which) { g_s2[c] = sc; g_t2[c] = sh; }
        else       { g_s1[c] = sc; g_t1[c] = sh; }
    }
}

// bnrelu + bf16 split for layer-2 input (into pool; p1 splits are dead)
__global__ void bnrelu_convert_kernel() {
    const size_t i = (size_t)blockIdx.x * 256 + threadIdx.x;
    float4 v = ((const float4*)g_h)[i];
    const int c4 = (int)(i & 63);
    const float4 sc = ((const float4*)g_s1)[c4];
    const float4 sh = ((const float4*)g_t1)[c4];
    v.x = fmaxf(fmaf(v.x, sc.x, sh.x), 0.f);
    v.y = fmaxf(fmaf(v.y, sc.y, sh.y), 0.f);
    v.z = fmaxf(fmaf(v.z, sc.z, sh.z), 0.f);
    v.w = fmaxf(fmaf(v.w, sc.w, sh.w), 0.f);
    union { __nv_bfloat16 bv[4]; uint2 u; } H, L;
    split_bf(v.x, H.bv[0], L.bv[0]);
    split_bf(v.y, H.bv[1], L.bv[1]);
    split_bf(v.z, H.bv[2], L.bv[2]);
    split_bf(v.w, H.bv[3], L.bv[3]);
    ((uint2*)g_ab)[i]                     = H.u;   // Bh
    ((uint2*)(g_ab + (size_t)MM * OO))[i] = L.u;   // Bl
}

// Final: out = relu(out*scale2 + shift2) in place
__global__ void bn_relu_kernel(float* __restrict__ X) {
    const size_t i = (size_t)blockIdx.x * 256 + threadIdx.x;
    float4 v = ((float4*)X)[i];
    const int c4 = (int)(i & 63);
    const float4 sc = ((const float4*)g_s2)[c4];
    const float4 sh = ((const float4*)g_t2)[c4];
    v.x = fmaxf(fmaf(v.x, sc.x, sh.x), 0.f);
    v.y = fmaxf(fmaf(v.y, sc.y, sh.y), 0.f);
    v.z = fmaxf(fmaf(v.z, sc.z, sh.z), 0.f);
    v.w = fmaxf(fmaf(v.w, sc.w, sh.w), 0.f);
    ((float4*)X)[i] = v;
}

// ======================================================================
extern "C" void kernel_launch(void* const* d_in, const int* in_sizes, int n_in,
                              void* d_out, int out_size) {
    const float* xyz1    = (const float*)d_in[0];
    const float* xyz2    = (const float*)d_in[1];
    const float* points1 = (const float*)d_in[2];
    const float* points2 = (const float*)d_in[3];
    const float* W1      = (const float*)d_in[4];
    const float* b1      = (const float*)d_in[5];
    const float* g1      = (const float*)d_in[6];
    const float* be1     = (const float*)d_in[7];
    const float* W2      = (const float*)d_in[8];
    const float* b2      = (const float*)d_in[9];
    const float* g2      = (const float*)d_in[10];
    const float* be2     = (const float*)d_in[11];
    float* out = (float*)d_out;

    cudaFuncSetAttribute(p2proj_kernel, cudaFuncAttributeMaxDynamicSharedMemorySize, GSMEM);
    cudaFuncSetAttribute(gemm1_kernel,  cudaFuncAttributeMaxDynamicSharedMemorySize, GSMEM);
    cudaFuncSetAttribute(gemm2_kernel,  cudaFuncAttributeMaxDynamicSharedMemorySize, GSMEM);

    wconvert_kernel<<<(OO * CF + 255) / 256, 256>>>(W1, W2);
    p2convert_kernel<<<(P2R * C2V / 4) / 256, 256>>>(points2);
    knn_kernel<<<dim3(NN / 512, BB), 256>>>(xyz1, xyz2, points1);

    p2proj_kernel<<<dim3(OO / 128, P2R / 128), NTHR, GSMEM>>>();
    gemm1_kernel<<<dim3(OO / 128, MM / 128), NTHR, GSMEM>>>(b1);
    bn_finalize_kernel<<<32, 256>>>(g1, be1, 0);
    bnrelu_convert_kernel<<<(MM * OO / 4) / 256, 256>>>();

    gemm2_kernel<<<dim3(OO / 128, MM / 128), NTHR, GSMEM>>>(b2, out);
    bn_finalize_kernel<<<32, 256>>>(g2, be2, 1);
    bn_relu_kernel<<<(MM * OO / 4) / 256, 256>>>(out);
}

// round 17
// speedup vs baseline: 1.0576x; 1.0576x over previous
#include <cuda_runtime.h>
#include <cuda_bf16.h>
#include <cstdint>
#include <math.h>

// Problem constants
#define BB 8
#define NN 16384
#define SSZ 2048
#define C1V 128
#define C2V 256
#define CF 384
#define MM (BB*NN)      /* 131072 rows */
#define OO 256          /* output channels per layer */
#define P2R (BB*SSZ)    /* 16384 points2 rows */

// -------- scratch (static device globals; ~308MB, below proven-safe 331MB) --------
// pool (134MB): phase1: p1h = [0, MM*128), p1l = [MM*128, 2*MM*128)
//               phase2: Bh  = [0, MM*256), Bl  = [MM*256, 2*MM*256)
__device__ __align__(16) __nv_bfloat16 g_ab[(size_t)2 * MM * OO];
__device__ __align__(16) float         g_h[(size_t)MM * OO];       // 134MB pre-BN h
__device__ __align__(16) float         g_p2proj[(size_t)P2R * OO]; // 16.8MB
__device__ __align__(16) __nv_bfloat16 g_p2h[(size_t)P2R * C2V];   // 8.4MB
__device__ __align__(16) __nv_bfloat16 g_p2l[(size_t)P2R * C2V];   // 8.4MB
__device__ __align__(16) float         g_knn[(size_t)MM * 8];      // 4MB idx+w
__device__ __align__(16) __nv_bfloat16 g_w1ah[OO * C1V], g_w1al[OO * C1V];
__device__ __align__(16) __nv_bfloat16 g_w1bh[OO * C2V], g_w1bl[OO * C2V];
__device__ __align__(16) __nv_bfloat16 g_w2h[OO * OO],  g_w2l[OO * OO];
__device__ __align__(16) float g_part[1024 * 512];                 // 2MB
__device__ __align__(16) float g_s1[OO], g_t1[OO], g_s2[OO], g_t2[OO];

// ======================================================================
// helpers (NO 'a'-suffix features)
// ======================================================================
__device__ __forceinline__ uint32_t smem_u32(const void* p) {
    uint32_t a;
    asm("{ .reg .u64 t; cvta.to.shared.u64 t, %1; cvt.u32.u64 %0, t; }" : "=r"(a) : "l"(p));
    return a;
}
__device__ __forceinline__ void cp_async16(uint32_t dst, const void* src) {
    asm volatile("cp.async.cg.shared.global [%0], [%1], 16;" :: "r"(dst), "l"(src));
}
#define CP_COMMIT() asm volatile("cp.async.commit_group;" ::: "memory")
#define CP_WAIT1()  asm volatile("cp.async.wait_group 1;" ::: "memory")
#define CP_WAIT0()  asm volatile("cp.async.wait_group 0;" ::: "memory")

#define LDSM4(r0, r1, r2, r3, addr) \
    asm volatile("ldmatrix.sync.aligned.m8n8.x4.shared.b16 {%0,%1,%2,%3}, [%4];" \
                 : "=r"(r0), "=r"(r1), "=r"(r2), "=r"(r3) : "r"(addr))

__device__ __forceinline__ void mma_bf16(float* c, const uint32_t* a, const uint32_t* b) {
    asm volatile("mma.sync.aligned.m16n8k16.row.col.f32.bf16.bf16.f32 "
                 "{%0,%1,%2,%3}, {%4,%5,%6,%7}, {%8,%9}, {%0,%1,%2,%3};"
                 : "+f"(c[0]), "+f"(c[1]), "+f"(c[2]), "+f"(c[3])
                 : "r"(a[0]), "r"(a[1]), "r"(a[2]), "r"(a[3]), "r"(b[0]), "r"(b[1]));
}

// bf16 hi/lo split (proven: rel_err 9.6e-6 end to end with 3-term products)
__device__ __forceinline__ void split_bf(float v, __nv_bfloat16& h, __nv_bfloat16& l) {
    h = __float2bfloat16_rn(v);
    l = __float2bfloat16_rn(v - __bfloat162float(h));
}

// ======================================================================
// Kernel 1: 3-NN (EXACT-DIFFERENCE distance — proven selection) + p1 split.
// Round-15 single-query version: 512 blocks (3.5 waves) beats 2-query/256
// blocks (1.7 waves, wave-quantized — round-16 regression).
// Expanded |q|^2-2p.q form flips neighbor ordering (1.4e-3). Never use it.
// ======================================================================
__global__ void knn_kernel(const float* __restrict__ xyz1,
                           const float* __restrict__ xyz2,
                           const float* __restrict__ points1) {
    __shared__ float4 s4[SSZ];

    const int tid = threadIdx.x;
    const int b   = blockIdx.y;
    const int n0  = blockIdx.x * 256;

    const float* x2 = xyz2 + (size_t)b * SSZ * 3;
    for (int s = tid; s < SSZ; s += 256) {
        s4[s] = make_float4(x2[3*s], x2[3*s+1], x2[3*s+2], 0.f);
    }
    __syncthreads();

    const int n = n0 + tid;
    const float* p = xyz1 + ((size_t)b * NN + n) * 3;
    const float px = p[0], py = p[1], pz = p[2];
    float b0 = 3.4e38f, b1 = 3.4e38f, b2 = 3.4e38f;
    int   j0 = 0, j1 = 0, j2 = 0;
    #pragma unroll 4
    for (int s = 0; s < SSZ; ++s) {
        float4 q = s4[s];
        float dx = px - q.x, dy = py - q.y, dz = pz - q.z;
        float d = dx*dx + dy*dy + dz*dz;
        if (d < b2) {
            if (d < b1) {
                b2 = b1; j2 = j1;
                if (d < b0) { b1 = b0; j1 = j0; b0 = d; j0 = s; }
                else        { b1 = d;  j1 = s; }
            } else { b2 = d; j2 = s; }
        }
    }
    float r0 = 1.f / (sqrtf(b0) + 1e-8f);
    float r1 = 1.f / (sqrtf(b1) + 1e-8f);
    float r2 = 1.f / (sqrtf(b2) + 1e-8f);
    float rs = 1.f / (r0 + r1 + r2);

    const size_t row = (size_t)b * NN + n;
    float4 ia, wa;
    ia.x = __int_as_float(b * SSZ + j0);
    ia.y = __int_as_float(b * SSZ + j1);
    ia.z = __int_as_float(b * SSZ + j2);
    ia.w = 0.f;
    wa.x = r0 * rs; wa.y = r1 * rs; wa.z = r2 * rs; wa.w = 0.f;
    ((float4*)g_knn)[row * 2]     = ia;
    ((float4*)g_knn)[row * 2 + 1] = wa;

    // points1 -> bf16 split into pool
    __nv_bfloat16* p1h = g_ab;
    __nv_bfloat16* p1l = g_ab + (size_t)MM * C1V;
    const float4* p1 = (const float4*)(points1 + ((size_t)b * NN + n0) * C1V);
    for (int i = tid; i < 256 * 32; i += 256) {
        float4 v = p1[i];
        union { __nv_bfloat16 bv[4]; uint2 u; } H, L;
        split_bf(v.x, H.bv[0], L.bv[0]);
        split_bf(v.y, H.bv[1], L.bv[1]);
        split_bf(v.z, H.bv[2], L.bv[2]);
        split_bf(v.w, H.bv[3], L.bv[3]);
        const size_t off4 = ((size_t)b * NN + n0) * 32 + i;
        ((uint2*)p1h)[off4] = H.u;
        ((uint2*)p1l)[off4] = L.u;
    }
}

// ======================================================================
// converts
// ======================================================================
__global__ void wconvert_kernel(const float* __restrict__ W1,
                                const float* __restrict__ W2) {
    int i = blockIdx.x * 256 + threadIdx.x;
    if (i < OO * CF) {
        int o = i / CF, c = i - o * CF;
        __nv_bfloat16 h, l; split_bf(W1[i], h, l);
        if (c < C1V) { g_w1ah[o * C1V + c] = h; g_w1al[o * C1V + c] = l; }
        else         { g_w1bh[o * C2V + c - C1V] = h; g_w1bl[o * C2V + c - C1V] = l; }
    }
    if (i < OO * OO) { __nv_bfloat16 h, l; split_bf(W2[i], h, l); g_w2h[i] = h; g_w2l[i] = l; }
}

__global__ void p2convert_kernel(const float* __restrict__ points2) {
    const size_t i = (size_t)blockIdx.x * 256 + threadIdx.x;
    float4 v = ((const float4*)points2)[i];
    union { __nv_bfloat16 bv[4]; uint2 u; } H, L;
    split_bf(v.x, H.bv[0], L.bv[0]);
    split_bf(v.y, H.bv[1], L.bv[1]);
    split_bf(v.z, H.bv[2], L.bv[2]);
    split_bf(v.w, H.bv[3], L.bv[3]);
    ((uint2*)g_p2h)[i] = H.u;
    ((uint2*)g_p2l)[i] = L.u;
}

// ======================================================================
// GEMM core (round-9/15, best measured): CTA 128x128, 512 threads / 16 warps
// (4m x 4n), warp 32x32, bf16 3-term, presplit cp.async, 3-stage.
// GRID ORDER (validated round 16): x = N-block (2), y = m-tile — adjacent
// blocks share the A tile so the second N-half's A-read hits L2.
// ======================================================================
#define ROWP 80
#define TILE_B (128 * ROWP)
#define STAGE_B (4 * TILE_B)
#define GSMEM   (3 * STAGE_B)      /* 122880 */
#define NTHR 512

struct FragIdx { uint32_t a_off, b_off; };
__device__ __forceinline__ FragIdx frag_idx(int lane) {
    const int g = lane >> 3, l7 = lane & 7;
    FragIdx f;
    f.a_off = (uint32_t)((l7 + (g & 1) * 8) * ROWP + (g >> 1) * 16);
    f.b_off = (uint32_t)(((g >> 1) * 8 + l7) * ROWP + (g & 1) * 16);
    return f;
}

__device__ __forceinline__ void compute_stage(uint32_t base, int warp_m, int warp_n,
                                              const FragIdx& f, float acc[2][4][4]) {
    #pragma unroll
    for (int ks = 0; ks < 2; ks++) {
        uint32_t ah[2][4], al[2][4], w[4][2];
        #pragma unroll
        for (int tm = 0; tm < 2; tm++) {
            const uint32_t ad = base + f.a_off + (uint32_t)((warp_m + tm * 16) * ROWP + ks * 32);
            LDSM4(ah[tm][0], ah[tm][1], ah[tm][2], ah[tm][3], ad);
            LDSM4(al[tm][0], al[tm][1], al[tm][2], al[tm][3], ad + TILE_B);
        }
        #pragma unroll
        for (int tp = 0; tp < 2; tp++) {
            const uint32_t bd = base + 2 * TILE_B + f.b_off
                              + (uint32_t)((warp_n + tp * 16) * ROWP + ks * 32);
            LDSM4(w[2*tp][0], w[2*tp][1], w[2*tp+1][0], w[2*tp+1][1], bd);
        }
        #pragma unroll
        for (int tm = 0; tm < 2; tm++)
            #pragma unroll
            for (int tn = 0; tn < 4; tn++) mma_bf16(acc[tm][tn], ah[tm], w[tn]);
        #pragma unroll
        for (int tm = 0; tm < 2; tm++)
            #pragma unroll
            for (int tn = 0; tn < 4; tn++) mma_bf16(acc[tm][tn], al[tm], w[tn]);
        #pragma unroll
        for (int tp = 0; tp < 2; tp++) {
            const uint32_t bd = base + 3 * TILE_B + f.b_off
                              + (uint32_t)((warp_n + tp * 16) * ROWP + ks * 32);
            LDSM4(w[2*tp][0], w[2*tp][1], w[2*tp+1][0], w[2*tp+1][1], bd);
        }
        #pragma unroll
        for (int tm = 0; tm < 2; tm++)
            #pragma unroll
            for (int tn = 0; tn < 4; tn++) mma_bf16(acc[tm][tn], ah[tm], w[tn]);
    }
}

template<bool BIAS, bool GATHER, bool PART>
__device__ __forceinline__ void gemm_epilogue(float acc[2][4][4], char* smem,
                                              int tid, int wid, int lane,
                                              int m0, int n0, int warp_m, int warp_n,
                                              const float* bias, float* C) {
    if (BIAS) {
        #pragma unroll
        for (int tn = 0; tn < 4; tn++) {
            float2 bv = *(const float2*)(bias + n0 + warp_n + tn * 8 + (lane & 3) * 2);
            #pragma unroll
            for (int tm = 0; tm < 2; tm++) {
                acc[tm][tn][0] += bv.x; acc[tm][tn][1] += bv.y;
                acc[tm][tn][2] += bv.x; acc[tm][tn][3] += bv.y;
            }
        }
    }
    if (GATHER) {
        #pragma unroll
        for (int tm = 0; tm < 2; tm++) {
            const int r_lo = m0 + warp_m + tm * 16 + (lane >> 2);
            const int r_hi = r_lo + 8;
            float4 ia = ((const float4*)g_knn)[(size_t)r_lo * 2];
            float4 wa = ((const float4*)g_knn)[(size_t)r_lo * 2 + 1];
            float4 ib = ((const float4*)g_knn)[(size_t)r_hi * 2];
            float4 wb = ((const float4*)g_knn)[(size_t)r_hi * 2 + 1];
            const int   gl[3] = { __float_as_int(ia.x), __float_as_int(ia.y), __float_as_int(ia.z) };
            const float wl[3] = { wa.x, wa.y, wa.z };
            const int   gh[3] = { __float_as_int(ib.x), __float_as_int(ib.y), __float_as_int(ib.z) };
            const float wh[3] = { wb.x, wb.y, wb.z };
            #pragma unroll
            for (int k = 0; k < 3; k++) {
                const float* pl = g_p2proj + (size_t)gl[k] * OO + n0;
                const float* ph = g_p2proj + (size_t)gh[k] * OO + n0;
                #pragma unroll
                for (int tn = 0; tn < 4; tn++) {
                    const int col = warp_n + tn * 8 + (lane & 3) * 2;
                    float2 vl = *(const float2*)(pl + col);
                    float2 vh = *(const float2*)(ph + col);
                    acc[tm][tn][0] += wl[k] * vl.x; acc[tm][tn][1] += wl[k] * vl.y;
                    acc[tm][tn][2] += wh[k] * vh.x; acc[tm][tn][3] += wh[k] * vh.y;
                }
            }
        }
    }
    if (PART) {
        __syncthreads();
        float* sP  = (float*)smem;        // [4][128]
        float* ssP = sP + 512;            // [4][128]
        const int mg = wid & 3;
        #pragma unroll
        for (int tn = 0; tn < 4; tn++) {
            #pragma unroll
            for (int p = 0; p < 2; p++) {
                float s = 0.f, ss = 0.f;
                #pragma unroll
                for (int tm = 0; tm < 2; tm++) {
                    float a = acc[tm][tn][p], b = acc[tm][tn][2 + p];
                    s += a + b; ss += a * a + b * b;
                }
                #pragma unroll
                for (int o = 4; o <= 16; o <<= 1) {
                    s  += __shfl_xor_sync(0xFFFFFFFFu, s, o);
                    ss += __shfl_xor_sync(0xFFFFFFFFu, ss, o);
                }
                if (lane < 4) {
                    const int cl = warp_n + tn * 8 + (lane & 3) * 2 + p;
                    sP [mg * 128 + cl] = s;
                    ssP[mg * 128 + cl] = ss;
                }
            }
        }
        __syncthreads();
        if (tid < 128) {
            const float s  = sP[tid]  + sP[128 + tid]  + sP[256 + tid]  + sP[384 + tid];
            const float ss = ssP[tid] + ssP[128 + tid] + ssP[256 + tid] + ssP[384 + tid];
            // m-tile = blockIdx.y under the swapped grid
            g_part[(size_t)blockIdx.y * 512 + n0 + tid]       = s;
            g_part[(size_t)blockIdx.y * 512 + 256 + n0 + tid] = ss;
        }
    }
    #pragma unroll
    for (int tm = 0; tm < 2; tm++) {
        const int r0 = m0 + warp_m + tm * 16 + (lane >> 2);
        float* c0 = C + (size_t)r0 * OO + n0;
        #pragma unroll
        for (int tn = 0; tn < 4; tn++) {
            const int col = warp_n + tn * 8 + (lane & 3) * 2;
            *(float2*)(c0 + col)          = make_float2(acc[tm][tn][0], acc[tm][tn][1]);
            *(float2*)(c0 + 8 * OO + col) = make_float2(acc[tm][tn][2], acc[tm][tn][3]);
        }
    }
}

// ----- presplit GEMM body (cp.async Ah/Al/Wh/Wl), 3-stage -----
// grid: x = N-block, y = m-tile (L2 reuse of A between the two N-halves)
template<int K, bool BIAS, bool GATHER, bool PART>
__device__ __forceinline__ void gemm_body(const __nv_bfloat16* __restrict__ Ah,
                                          const __nv_bfloat16* __restrict__ Al,
                                          const __nv_bfloat16* __restrict__ Wh,
                                          const __nv_bfloat16* __restrict__ Wl,
                                          const float* __restrict__ bias,
                                          float* __restrict__ C) {
    extern __shared__ char smem[];
    constexpr int NC = K / 32;
    const uint32_t sb = smem_u32(smem);
    const int tid  = threadIdx.x;
    const int wid  = tid >> 5, lane = tid & 31;
    const int m0   = blockIdx.y << 7;
    const int n0   = blockIdx.x << 7;
    const int warp_m = (wid & 3) * 32;
    const int warp_n = (wid >> 2) * 32;

    const int lr = tid >> 2, lkg = tid & 3;
    const uint32_t l_dst = (uint32_t)(lr * ROWP + lkg * 16);
    const size_t   a_src0 = (size_t)(m0 + lr) * K + lkg * 8;
    const size_t   w_src0 = (size_t)(n0 + lr) * K + lkg * 8;
    const FragIdx f = frag_idx(lane);

    float acc[2][4][4];
    #pragma unroll
    for (int tm = 0; tm < 2; tm++)
        #pragma unroll
        for (int tn = 0; tn < 4; tn++)
            #pragma unroll
            for (int q = 0; q < 4; q++) acc[tm][tn][q] = 0.f;

    auto load_stage = [&](int s, int kc) {
        const uint32_t base = sb + s * STAGE_B;
        cp_async16(base + l_dst,              Ah + a_src0 + kc);
        cp_async16(base + l_dst + TILE_B,     Al + a_src0 + kc);
        cp_async16(base + l_dst + 2 * TILE_B, Wh + w_src0 + kc);
        cp_async16(base + l_dst + 3 * TILE_B, Wl + w_src0 + kc);
    };

    load_stage(0, 0);  CP_COMMIT();
    load_stage(1, 32); CP_COMMIT();

    for (int i = 0; i < NC; i++) {
        if (i + 1 < NC) { CP_WAIT1(); } else { CP_WAIT0(); }
        __syncthreads();
        if (i + 2 < NC) { load_stage((i + 2) % 3, (i + 2) * 32); CP_COMMIT(); }
        compute_stage(sb + (i % 3) * STAGE_B, warp_m, warp_n, f, acc);
    }
    gemm_epilogue<BIAS, GATHER, PART>(acc, smem, tid, wid, lane, m0, n0, warp_m, warp_n, bias, C);
}

__global__ void __launch_bounds__(NTHR, 1)
p2proj_kernel() {
    gemm_body<C2V, false, false, false>(g_p2h, g_p2l, g_w1bh, g_w1bl, nullptr, g_p2proj);
}
__global__ void __launch_bounds__(NTHR, 1)
gemm1_kernel(const float* __restrict__ bias) {
    gemm_body<C1V, true, true, true>(g_ab, g_ab + (size_t)MM * C1V, g_w1ah, g_w1al, bias, g_h);
}
__global__ void __launch_bounds__(NTHR, 1)
gemm2_kernel(const float* __restrict__ bias, float* __restrict__ C) {
    gemm_body<OO, true, false, true>(g_ab, g_ab + (size_t)MM * OO, g_w2h, g_w2l, bias, C);
}

// ======================================================================
// BN finalize over 1024 m-block partials; 32 blocks x 8 warps
// ======================================================================
__global__ void bn_finalize_kernel(const float* __restrict__ g,
                                   const float* __restrict__ be, int which) {
    const int w = threadIdx.x >> 5, l = threadIdx.x & 31;
    const int c = blockIdx.x * 8 + w;
    float s = 0.f, ss = 0.f;
    for (int b = l; b < 1024; b += 32) {
        s  += g_part[(size_t)b * 512 + c];
        ss += g_part[(size_t)b * 512 + 256 + c];
    }
    #pragma unroll
    for (int o = 16; o; o >>= 1) {
        s  += __shfl_xor_sync(0xFFFFFFFFu, s, o);
        ss += __shfl_xor_sync(0xFFFFFFFFu, ss, o);
    }
    if (l == 0) {
        const float mu  = s * (1.0f / (float)MM);
        const float var = ss * (1.0f / (float)MM) - mu * mu;
        const float inv = rsqrtf(var + 1e-5f);
        const float sc  = g[c] * inv;
        const float sh  = be[c] - mu * sc;
        if (which) { g_s2[c] = sc; g_t2[c] = sh; }
        else       { g_s1[c] = sc; g_t1[c] = sh; }
    }
}

// bnrelu + bf16 split for layer-2 input (into pool; p1 splits are dead)
__global__ void bnrelu_convert_kernel() {
    const size_t i = (size_t)blockIdx.x * 256 + threadIdx.x;
    float4 v = ((const float4*)g_h)[i];
    const int c4 = (int)(i & 63);
    const float4 sc = ((const float4*)g_s1)[c4];
    const float4 sh = ((const float4*)g_t1)[c4];
    v.x = fmaxf(fmaf(v.x, sc.x, sh.x), 0.f);
    v.y = fmaxf(fmaf(v.y, sc.y, sh.y), 0.f);
    v.z = fmaxf(fmaf(v.z, sc.z, sh.z), 0.f);
    v.w = fmaxf(fmaf(v.w, sc.w, sh.w), 0.f);
    union { __nv_bfloat16 bv[4]; uint2 u; } H, L;
    split_bf(v.x, H.bv[0], L.bv[0]);
    split_bf(v.y, H.bv[1], L.bv[1]);
    split_bf(v.z, H.bv[2], L.bv[2]);
    split_bf(v.w, H.bv[3], L.bv[3]);
    ((uint2*)g_ab)[i]                     = H.u;   // Bh
    ((uint2*)(g_ab + (size_t)MM * OO))[i] = L.u;   // Bl
}

// Final: out = relu(out*scale2 + shift2) in place
__global__ void bn_relu_kernel(float* __restrict__ X) {
    const size_t i = (size_t)blockIdx.x * 256 + threadIdx.x;
    float4 v = ((float4*)X)[i];
    const int c4 = (int)(i & 63);
    const float4 sc = ((const float4*)g_s2)[c4];
    const float4 sh = ((const float4*)g_t2)[c4];
    v.x = fmaxf(fmaf(v.x, sc.x, sh.x), 0.f);
    v.y = fmaxf(fmaf(v.y, sc.y, sh.y), 0.f);
    v.z = fmaxf(fmaf(v.z, sc.z, sh.z), 0.f);
    v.w = fmaxf(fmaf(v.w, sc.w, sh.w), 0.f);
    ((float4*)X)[i] = v;
}

// ======================================================================
extern "C" void kernel_launch(void* const* d_in, const int* in_sizes, int n_in,
                              void* d_out, int out_size) {
    const float* xyz1    = (const float*)d_in[0];
    const float* xyz2    = (const float*)d_in[1];
    const float* points1 = (const float*)d_in[2];
    const float* points2 = (const float*)d_in[3];
    const float* W1      = (const float*)d_in[4];
    const float* b1      = (const float*)d_in[5];
    const float* g1      = (const float*)d_in[6];
    const float* be1     = (const float*)d_in[7];
    const float* W2      = (const float*)d_in[8];
    const float* b2      = (const float*)d_in[9];
    const float* g2      = (const float*)d_in[10];
    const float* be2     = (const float*)d_in[11];
    float* out = (float*)d_out;

    cudaFuncSetAttribute(p2proj_kernel, cudaFuncAttributeMaxDynamicSharedMemorySize, GSMEM);
    cudaFuncSetAttribute(gemm1_kernel,  cudaFuncAttributeMaxDynamicSharedMemorySize, GSMEM);
    cudaFuncSetAttribute(gemm2_kernel,  cudaFuncAttributeMaxDynamicSharedMemorySize, GSMEM);

    wconvert_kernel<<<(OO * CF + 255) / 256, 256>>>(W1, W2);
    p2convert_kernel<<<(P2R * C2V / 4) / 256, 256>>>(points2);
    knn_kernel<<<dim3(NN / 256, BB), 256>>>(xyz1, xyz2, points1);

    p2proj_kernel<<<dim3(OO / 128, P2R / 128), NTHR, GSMEM>>>();
    gemm1_kernel<<<dim3(OO / 128, MM / 128), NTHR, GSMEM>>>(b1);
    bn_finalize_kernel<<<32, 256>>>(g1, be1, 0);
    bnrelu_convert_kernel<<<(MM * OO / 4) / 256, 256>>>();

    gemm2_kernel<<<dim3(OO / 128, MM / 128), NTHR, GSMEM>>>(b2, out);
    bn_finalize_kernel<<<32, 256>>>(g2, be2, 1);
    bn_relu_kernel<<<(MM * OO / 4) / 256, 256>>>(out);
}